// round 2
// baseline (speedup 1.0000x reference)
#include <cuda_runtime.h>

#define BB 2
#define SS 2048
#define DM 1024
#define NH 16
#define DK 64
#define WIN 512

// Scratch (device globals — no allocation allowed)
__device__ float g_q[BB*NH*SS*DK];
__device__ float g_k[BB*NH*SS*DK];
__device__ float g_v[BB*NH*SS*DK];
__device__ float g_attn[BB*SS*DM];

// ---------------------------------------------------------------------------
// SGEMM 128x128x8, 256 threads, 8x8 per thread with strided (tx+16j) ownership
// (conflict-free smem reads). Used twice with different epilogues.
// ---------------------------------------------------------------------------

__global__ __launch_bounds__(256) void gemm_qkv_kernel(
    const float* __restrict__ A,   // x: [4096, 1024]
    const float* __restrict__ Bw)  // w_qkv: [1024, 3072]
{
    const int K = DM;
    const int N = 3 * DM;
    __shared__ float As[8][132];   // [k][m], padded
    __shared__ float Bs[8][128];   // [k][n]

    int tid = threadIdx.x;
    int ty = tid >> 4, tx = tid & 15;
    int m0 = blockIdx.y * 128;
    int n0 = blockIdx.x * 128;

    float acc[8][8];
#pragma unroll
    for (int i = 0; i < 8; i++)
#pragma unroll
        for (int j = 0; j < 8; j++) acc[i][j] = 0.f;

    int arow = tid >> 1, apart = tid & 1;      // A: 128 rows x 2 float4
    int brow = tid >> 5, bc4  = tid & 31;      // B: 8 rows x 32 float4

    for (int kt = 0; kt < K / 8; kt++) {
        float4 av = *(const float4*)&A[(m0 + arow) * K + kt * 8 + apart * 4];
        As[apart * 4 + 0][arow] = av.x;
        As[apart * 4 + 1][arow] = av.y;
        As[apart * 4 + 2][arow] = av.z;
        As[apart * 4 + 3][arow] = av.w;
        float4 bv = *(const float4*)&Bw[(kt * 8 + brow) * N + n0 + bc4 * 4];
        *(float4*)&Bs[brow][bc4 * 4] = bv;
        __syncthreads();
#pragma unroll
        for (int k = 0; k < 8; k++) {
            float a[8], b[8];
#pragma unroll
            for (int i = 0; i < 8; i++) a[i] = As[k][ty + 16 * i];
#pragma unroll
            for (int j = 0; j < 8; j++) b[j] = Bs[k][tx + 16 * j];
#pragma unroll
            for (int i = 0; i < 8; i++)
#pragma unroll
                for (int j = 0; j < 8; j++) acc[i][j] += a[i] * b[j];
        }
        __syncthreads();
    }

    // Scatter epilogue: column n -> (part, head, d); row m -> (b, s)
    int part = n0 >> 10;  // uniform per block (128 | 1024)
    float* dst = (part == 0) ? g_q : ((part == 1) ? g_k : g_v);
#pragma unroll
    for (int i = 0; i < 8; i++) {
        int m = m0 + ty + 16 * i;
        int b = m >> 11;
        int s = m & (SS - 1);
#pragma unroll
        for (int j = 0; j < 8; j++) {
            int n = n0 + tx + 16 * j;
            int h = (n & 1023) >> 6;
            int d = n & 63;
            dst[((b * NH + h) * SS + s) * DK + d] = acc[i][j];
        }
    }
}

__global__ __launch_bounds__(256) void gemm_out_kernel(
    const float* __restrict__ Bw,  // w_o: [1024, 1024]
    float* __restrict__ C)         // out: [4096, 1024]
{
    const int K = DM;
    const int N = DM;
    const float* A = g_attn;
    __shared__ float As[8][132];
    __shared__ float Bs[8][128];

    int tid = threadIdx.x;
    int ty = tid >> 4, tx = tid & 15;
    int m0 = blockIdx.y * 128;
    int n0 = blockIdx.x * 128;

    float acc[8][8];
#pragma unroll
    for (int i = 0; i < 8; i++)
#pragma unroll
        for (int j = 0; j < 8; j++) acc[i][j] = 0.f;

    int arow = tid >> 1, apart = tid & 1;
    int brow = tid >> 5, bc4  = tid & 31;

    for (int kt = 0; kt < K / 8; kt++) {
        float4 av = *(const float4*)&A[(m0 + arow) * K + kt * 8 + apart * 4];
        As[apart * 4 + 0][arow] = av.x;
        As[apart * 4 + 1][arow] = av.y;
        As[apart * 4 + 2][arow] = av.z;
        As[apart * 4 + 3][arow] = av.w;
        float4 bv = *(const float4*)&Bw[(kt * 8 + brow) * N + n0 + bc4 * 4];
        *(float4*)&Bs[brow][bc4 * 4] = bv;
        __syncthreads();
#pragma unroll
        for (int k = 0; k < 8; k++) {
            float a[8], b[8];
#pragma unroll
            for (int i = 0; i < 8; i++) a[i] = As[k][ty + 16 * i];
#pragma unroll
            for (int j = 0; j < 8; j++) b[j] = Bs[k][tx + 16 * j];
#pragma unroll
            for (int i = 0; i < 8; i++)
#pragma unroll
                for (int j = 0; j < 8; j++) acc[i][j] += a[i] * b[j];
        }
        __syncthreads();
    }

#pragma unroll
    for (int i = 0; i < 8; i++) {
        int m = m0 + ty + 16 * i;
#pragma unroll
        for (int j = 0; j < 8; j++) {
            int n = n0 + tx + 16 * j;
            C[m * N + n] = acc[i][j];
        }
    }
}

// ---------------------------------------------------------------------------
// RoPE in place on g_q and g_k. One thread per (even,odd) pair.
// total pairs = 2 arrays * B*H*S*32 = 4,194,304
// ---------------------------------------------------------------------------
__global__ void rope_kernel() {
    int idx = blockIdx.x * blockDim.x + threadIdx.x;
    const int half_total = BB * NH * SS * (DK / 2);  // 2^21
    float* arr = (idx < half_total) ? g_q : g_k;
    int p = idx & (half_total - 1);
    int d2 = p & 31;
    int s = (p >> 5) & (SS - 1);
    int bh = p >> 16;
    int off = (bh * SS + s) * DK + 2 * d2;
    float inv = powf(10000.0f, -(float)d2 * (1.0f / 32.0f));
    float ang = (float)s * inv;
    float c = cosf(ang);
    float si = sinf(ang);
    float e = arr[off];
    float o = arr[off + 1];
    arr[off]     = e * c - o * si;
    arr[off + 1] = o * c + e * si;
}

// ---------------------------------------------------------------------------
// Sliding-window flash attention.
// One CTA: (b, h, 64-query block). 256 threads; thread (ty,tx) owns
// rows {ty+16i} x cols {tx+16j}. Row state (m, l) is register-resident,
// reduced over the 16-lane half-warp that owns each row.
// smem: Qs[64*65] | KsP[64*65] (K tile, then reused for P) | Vs[64*65]
// ---------------------------------------------------------------------------
#define AT_STR 65
#define AT_SMEM_FLOATS (3 * 64 * AT_STR)

__global__ __launch_bounds__(256) void attn_kernel() {
    extern __shared__ float sm[];
    float* Qs  = sm;
    float* KsP = sm + 64 * AT_STR;
    float* Vs  = sm + 2 * 64 * AT_STR;

    int tid = threadIdx.x;
    int ty = tid >> 4, tx = tid & 15;
    int q0 = blockIdx.x * 64;
    int h = blockIdx.y;
    int b = blockIdx.z;

    const float* Qg = g_q + (size_t)((b * NH + h) * SS) * DK;
    const float* Kg = g_k + (size_t)((b * NH + h) * SS) * DK;
    const float* Vg = g_v + (size_t)((b * NH + h) * SS) * DK;

    // Load Q tile (64x64), scalar stores into padded smem
#pragma unroll
    for (int it = 0; it < 4; it++) {
        int f = tid + it * 256;
        int r = f >> 4, c4 = f & 15;
        float4 v = *(const float4*)&Qg[(q0 + r) * DK + c4 * 4];
        Qs[r * AT_STR + c4 * 4 + 0] = v.x;
        Qs[r * AT_STR + c4 * 4 + 1] = v.y;
        Qs[r * AT_STR + c4 * 4 + 2] = v.z;
        Qs[r * AT_STR + c4 * 4 + 3] = v.w;
    }

    float acc[4][4];
    float mrow[4], lrow[4];
#pragma unroll
    for (int i = 0; i < 4; i++) {
        mrow[i] = -1e30f;
        lrow[i] = 0.f;
#pragma unroll
        for (int j = 0; j < 4; j++) acc[i][j] = 0.f;
    }

    int first = (q0 >= WIN) ? (q0 - WIN) : 0;
    int ntiles = (q0 + 63 - first) / 64 + 1;

    for (int t = 0; t < ntiles; t++) {
        int k0 = first + t * 64;
        __syncthreads();  // protect KsP/Vs from previous tile's readers
        // Load K and V tiles (row-major [key][d], padded)
#pragma unroll
        for (int it = 0; it < 4; it++) {
            int f = tid + it * 256;
            int r = f >> 4, c4 = f & 15;
            float4 kv = *(const float4*)&Kg[(k0 + r) * DK + c4 * 4];
            KsP[r * AT_STR + c4 * 4 + 0] = kv.x;
            KsP[r * AT_STR + c4 * 4 + 1] = kv.y;
            KsP[r * AT_STR + c4 * 4 + 2] = kv.z;
            KsP[r * AT_STR + c4 * 4 + 3] = kv.w;
            float4 vv = *(const float4*)&Vg[(k0 + r) * DK + c4 * 4];
            Vs[r * AT_STR + c4 * 4 + 0] = vv.x;
            Vs[r * AT_STR + c4 * 4 + 1] = vv.y;
            Vs[r * AT_STR + c4 * 4 + 2] = vv.z;
            Vs[r * AT_STR + c4 * 4 + 3] = vv.w;
        }
        __syncthreads();

        // S = Q @ K^T (scaled, masked)
        float sreg[4][4];
#pragma unroll
        for (int i = 0; i < 4; i++)
#pragma unroll
            for (int j = 0; j < 4; j++) sreg[i][j] = 0.f;
#pragma unroll 8
        for (int d = 0; d < 64; d++) {
            float qa[4], kb[4];
#pragma unroll
            for (int i = 0; i < 4; i++) qa[i] = Qs[(ty + 16 * i) * AT_STR + d];
#pragma unroll
            for (int j = 0; j < 4; j++) kb[j] = KsP[(tx + 16 * j) * AT_STR + d];
#pragma unroll
            for (int i = 0; i < 4; i++)
#pragma unroll
                for (int j = 0; j < 4; j++) sreg[i][j] += qa[i] * kb[j];
        }
#pragma unroll
        for (int i = 0; i < 4; i++) {
            int iq = q0 + ty + 16 * i;
#pragma unroll
            for (int j = 0; j < 4; j++) {
                int jk = k0 + tx + 16 * j;
                bool ok = (jk <= iq) && (jk >= iq - WIN);
                sreg[i][j] = ok ? sreg[i][j] * 0.125f : -1e30f;
            }
        }

        // Online softmax: row r = ty+16i lives in one 16-lane half-warp.
        float corr[4];
#pragma unroll
        for (int i = 0; i < 4; i++) {
            float tmax = fmaxf(fmaxf(sreg[i][0], sreg[i][1]),
                               fmaxf(sreg[i][2], sreg[i][3]));
#pragma unroll
            for (int off = 8; off >= 1; off >>= 1)
                tmax = fmaxf(tmax, __shfl_xor_sync(0xffffffffu, tmax, off, 16));
            float mn = fmaxf(mrow[i], tmax);
            corr[i] = __expf(mrow[i] - mn);
            mrow[i] = mn;
        }

        __syncthreads();  // everyone done reading KsP: safe to overwrite with P
#pragma unroll
        for (int i = 0; i < 4; i++) {
            float psum = 0.f;
#pragma unroll
            for (int j = 0; j < 4; j++) {
                float p = __expf(sreg[i][j] - mrow[i]);
                KsP[(ty + 16 * i) * AT_STR + tx + 16 * j] = p;
                psum += p;
                acc[i][j] *= corr[i];
            }
#pragma unroll
            for (int off = 8; off >= 1; off >>= 1)
                psum += __shfl_xor_sync(0xffffffffu, psum, off, 16);
            lrow[i] = lrow[i] * corr[i] + psum;
        }
        __syncthreads();

        // acc += P @ V
#pragma unroll 8
        for (int k = 0; k < 64; k++) {
            float pa[4], vb[4];
#pragma unroll
            for (int i = 0; i < 4; i++) pa[i] = KsP[(ty + 16 * i) * AT_STR + k];
#pragma unroll
            for (int j = 0; j < 4; j++) vb[j] = Vs[k * AT_STR + tx + 16 * j];
#pragma unroll
            for (int i = 0; i < 4; i++)
#pragma unroll
                for (int j = 0; j < 4; j++) acc[i][j] += pa[i] * vb[j];
        }
    }

    // Write normalized output to g_attn in [B, S, H*DK] layout
#pragma unroll
    for (int i = 0; i < 4; i++) {
        int s = q0 + ty + 16 * i;
        float inv_l = 1.0f / lrow[i];
#pragma unroll
        for (int j = 0; j < 4; j++) {
            g_attn[(size_t)(b * SS + s) * DM + h * DK + tx + 16 * j] =
                acc[i][j] * inv_l;
        }
    }
}

// ---------------------------------------------------------------------------

extern "C" void kernel_launch(void* const* d_in, const int* in_sizes, int n_in,
                              void* d_out, int out_size) {
    const float* x     = (const float*)d_in[0];
    const float* w_qkv = (const float*)d_in[1];
    const float* w_o   = (const float*)d_in[2];
    float* out = (float*)d_out;

    // 1) QKV projection (scatter into g_q/g_k/g_v)
    gemm_qkv_kernel<<<dim3(3 * DM / 128, BB * SS / 128), 256>>>(x, w_qkv);

    // 2) RoPE on q and k
    rope_kernel<<<(2 * BB * NH * SS * (DK / 2)) / 256, 256>>>();

    // 3) Sliding-window attention
    cudaFuncSetAttribute(attn_kernel, cudaFuncAttributeMaxDynamicSharedMemorySize,
                         AT_SMEM_FLOATS * (int)sizeof(float));
    attn_kernel<<<dim3(SS / 64, NH, BB), 256,
                  AT_SMEM_FLOATS * sizeof(float)>>>();

    // 4) Output projection
    gemm_out_kernel<<<dim3(DM / 128, BB * SS / 128), 256>>>(w_o, out);
}

// round 10
// speedup vs baseline: 1.7182x; 1.7182x over previous
#include <cuda_runtime.h>
#include <cuda_bf16.h>
#include <cstdint>

#define BB 2
#define SS 2048
#define DM 1024
#define NH 16
#define DK 64
#define WIN 512

// ------------------------- scratch (device globals) -------------------------
__device__ float g_q[BB*NH*SS*DK];
__device__ float g_k[BB*NH*SS*DK];
__device__ float g_v[BB*NH*SS*DK];
__device__ __align__(256) __nv_bfloat16 g_x_hi[BB*SS*DM];
__device__ __align__(256) __nv_bfloat16 g_x_lo[BB*SS*DM];
__device__ __align__(256) __nv_bfloat16 g_wq_hi[3*DM*DM];
__device__ __align__(256) __nv_bfloat16 g_wq_lo[3*DM*DM];
__device__ __align__(256) __nv_bfloat16 g_wo_hi[DM*DM];
__device__ __align__(256) __nv_bfloat16 g_wo_lo[DM*DM];
__device__ __align__(256) __nv_bfloat16 g_at_hi[BB*SS*DM];
__device__ __align__(256) __nv_bfloat16 g_at_lo[BB*SS*DM];

// ------------------------------ helpers -------------------------------------
__device__ __forceinline__ void mma_bf16(float* d, const uint32_t* a,
                                         const uint32_t* b) {
    asm volatile(
        "mma.sync.aligned.m16n8k16.row.col.f32.bf16.bf16.f32 "
        "{%0,%1,%2,%3}, {%4,%5,%6,%7}, {%8,%9}, {%0,%1,%2,%3};"
        : "+f"(d[0]), "+f"(d[1]), "+f"(d[2]), "+f"(d[3])
        : "r"(a[0]), "r"(a[1]), "r"(a[2]), "r"(a[3]), "r"(b[0]), "r"(b[1]));
}

// ------------- bf16x3 HMMA GEMM mainloop: 128x128 CTA, K=1024 ---------------
// Static smem: 4 tiles (Ah, Al, Bh, Bl), each 128 rows x 32 bf16, stride 40.
// Fragments via plain LDS.32 at PTX m16n8k16 fragment coordinates:
//   a0=A[m=q][k=2c], a1=A[q+8][2c], a2=A[q][2c+8], a3=A[q+8][2c+8]
//   b0=B[n=q][2c],  b1=B[q][2c+8]            (q=lane/4, c=lane%4)
// Bank check (stride 40 elems = 20 banks): bank = 20*q + c  -> 0..31 perm.
#define MM_STR 40
#define MM_TILE (128 * MM_STR)           // 5120 elements per tile

__device__ __forceinline__ void mma_mainloop(
    __nv_bfloat16* sm,
    const __nv_bfloat16* __restrict__ Ah, const __nv_bfloat16* __restrict__ Al,
    const __nv_bfloat16* __restrict__ Bh, const __nv_bfloat16* __restrict__ Bl,
    int m0, int n0, float acc[4][4][4])
{
    int tid = threadIdx.x;
    int wid = tid >> 5, lane = tid & 31;
    int wm = wid & 1, wn = wid >> 1;        // warp tile: rows wm*64, cols wn*32
    int qr = lane >> 2;                     // 0..7
    int qc = (lane & 3) * 2;                // 0,2,4,6

#pragma unroll
    for (int mi = 0; mi < 4; mi++)
#pragma unroll
        for (int ni = 0; ni < 4; ni++)
#pragma unroll
            for (int k = 0; k < 4; k++) acc[mi][ni][k] = 0.f;

    __nv_bfloat16* tA[2] = { sm,              sm + MM_TILE };      // Ah, Al
    __nv_bfloat16* tB[2] = { sm + 2*MM_TILE,  sm + 3*MM_TILE };    // Bh, Bl

    for (int t = 0; t < 32; t++) {          // K chunks of 32
        __syncthreads();                    // previous stage's readers done
#pragma unroll
        for (int tile = 0; tile < 4; tile++) {
            const __nv_bfloat16* src;
            int rb;
            if      (tile == 0) { src = Ah; rb = m0; }
            else if (tile == 1) { src = Al; rb = m0; }
            else if (tile == 2) { src = Bh; rb = n0; }
            else                { src = Bl; rb = n0; }
            __nv_bfloat16* dst = sm + tile * MM_TILE;
#pragma unroll
            for (int it = 0; it < 2; it++) {
                int idx = tid + it * 256;
                int r = idx >> 2, c = idx & 3;
                uint4 v = *(const uint4*)(src + (size_t)(rb + r) * DM + t * 32 + c * 8);
                *(uint4*)(dst + r * MM_STR + c * 8) = v;
            }
        }
        __syncthreads();

        // 3 split terms: Ah*Bh, Ah*Bl, Al*Bh
#pragma unroll
        for (int term = 0; term < 3; term++) {
            const __nv_bfloat16* At = tA[term == 2 ? 1 : 0];
            const __nv_bfloat16* Bt = tB[term == 1 ? 1 : 0];
#pragma unroll
            for (int kk = 0; kk < 2; kk++) {         // k16 steps
                int kc = kk * 16 + qc;
                uint32_t afr[4][4], bfr[4][2];
#pragma unroll
                for (int mi = 0; mi < 4; mi++) {
                    int row = wm * 64 + mi * 16 + qr;
                    afr[mi][0] = *(const uint32_t*)(At + row * MM_STR + kc);
                    afr[mi][1] = *(const uint32_t*)(At + (row + 8) * MM_STR + kc);
                    afr[mi][2] = *(const uint32_t*)(At + row * MM_STR + kc + 8);
                    afr[mi][3] = *(const uint32_t*)(At + (row + 8) * MM_STR + kc + 8);
                }
#pragma unroll
                for (int ni = 0; ni < 4; ni++) {
                    int brow = wn * 32 + ni * 8 + qr;
                    bfr[ni][0] = *(const uint32_t*)(Bt + brow * MM_STR + kc);
                    bfr[ni][1] = *(const uint32_t*)(Bt + brow * MM_STR + kc + 8);
                }
#pragma unroll
                for (int mi = 0; mi < 4; mi++)
#pragma unroll
                    for (int ni = 0; ni < 4; ni++)
                        mma_bf16(acc[mi][ni], afr[mi], bfr[ni]);
            }
        }
    }
}

// ---------------------------- QKV projection GEMM ---------------------------
__global__ __launch_bounds__(256) void mma_gemm_qkv() {
    __shared__ __nv_bfloat16 smem[4 * MM_TILE];   // 40960 B static
    int m0 = blockIdx.y * 128, n0 = blockIdx.x * 128;
    float acc[4][4][4];
    mma_mainloop(smem, g_x_hi, g_x_lo, g_wq_hi, g_wq_lo, m0, n0, acc);

    int tid = threadIdx.x, wid = tid >> 5, lane = tid & 31;
    int wm = wid & 1, wn = wid >> 1;
    int g = lane >> 2, tt = lane & 3;

    int ncol = n0 + wn * 32;                 // warp col base (32-aligned)
    int part = n0 >> 10;                     // q/k/v (uniform per block)
    int hh = (ncol & 1023) >> 6;             // head (uniform per warp)
    int d0 = ncol & 63;                      // 0 or 32
    float* dst = (part == 0) ? g_q : ((part == 1) ? g_k : g_v);

#pragma unroll
    for (int mi = 0; mi < 4; mi++) {
#pragma unroll
        for (int half = 0; half < 2; half++) {
            int m = m0 + wm * 64 + mi * 16 + g + half * 8;
            int b = m >> 11, s = m & (SS - 1);
            float* p = dst + ((size_t)((b * NH + hh) * SS + s)) * DK;
#pragma unroll
            for (int ni = 0; ni < 4; ni++) {
                float2 v;
                v.x = acc[mi][ni][half * 2 + 0];
                v.y = acc[mi][ni][half * 2 + 1];
                *(float2*)(p + d0 + ni * 8 + tt * 2) = v;
            }
        }
    }
}

// ------------------------------- output GEMM --------------------------------
__global__ __launch_bounds__(256) void mma_gemm_out(float* __restrict__ C) {
    __shared__ __nv_bfloat16 smem[4 * MM_TILE];
    int m0 = blockIdx.y * 128, n0 = blockIdx.x * 128;
    float acc[4][4][4];
    mma_mainloop(smem, g_at_hi, g_at_lo, g_wo_hi, g_wo_lo, m0, n0, acc);

    int tid = threadIdx.x, wid = tid >> 5, lane = tid & 31;
    int wm = wid & 1, wn = wid >> 1;
    int g = lane >> 2, tt = lane & 3;
#pragma unroll
    for (int mi = 0; mi < 4; mi++) {
#pragma unroll
        for (int half = 0; half < 2; half++) {
            int m = m0 + wm * 64 + mi * 16 + g + half * 8;
            float* p = C + (size_t)m * DM + n0 + wn * 32;
#pragma unroll
            for (int ni = 0; ni < 4; ni++) {
                float2 v;
                v.x = acc[mi][ni][half * 2 + 0];
                v.y = acc[mi][ni][half * 2 + 1];
                *(float2*)(p + ni * 8 + tt * 2) = v;
            }
        }
    }
}

// ------------------------- convert / transpose kernels ----------------------
// NOTE: device globals are referenced ONLY inside device code (host code must
// never pass a __device__ symbol as a kernel argument — on GB300/ATS that
// silently writes host memory instead of faulting).
__global__ void conv_split(const float* __restrict__ s) {
    int i = (blockIdx.x * 256 + threadIdx.x) * 4;
    __nv_bfloat16* hi = g_x_hi;
    __nv_bfloat16* lo = g_x_lo;
    float4 v = *(const float4*)(s + i);
    __nv_bfloat16 h0 = __float2bfloat16(v.x), h1 = __float2bfloat16(v.y);
    __nv_bfloat16 h2 = __float2bfloat16(v.z), h3 = __float2bfloat16(v.w);
    __nv_bfloat162 H0; H0.x = h0; H0.y = h1;
    __nv_bfloat162 H1; H1.x = h2; H1.y = h3;
    *(__nv_bfloat162*)(hi + i)     = H0;
    *(__nv_bfloat162*)(hi + i + 2) = H1;
    __nv_bfloat162 L0, L1;
    L0.x = __float2bfloat16(v.x - __bfloat162float(h0));
    L0.y = __float2bfloat16(v.y - __bfloat162float(h1));
    L1.x = __float2bfloat16(v.z - __bfloat162float(h2));
    L1.y = __float2bfloat16(v.w - __bfloat162float(h3));
    *(__nv_bfloat162*)(lo + i)     = L0;
    *(__nv_bfloat162*)(lo + i + 2) = L1;
}

__global__ void conv_wT(const float* __restrict__ w, int which, int K, int N) {
    __nv_bfloat16* th = which ? g_wo_hi : g_wq_hi;
    __nv_bfloat16* tl = which ? g_wo_lo : g_wq_lo;
    __shared__ float t[32][33];
    int n0 = blockIdx.x * 32, k0 = blockIdx.y * 32;
    int tx = threadIdx.x, ty = threadIdx.y;
#pragma unroll
    for (int i = 0; i < 4; i++)
        t[ty + 8 * i][tx] = w[(size_t)(k0 + ty + 8 * i) * N + n0 + tx];
    __syncthreads();
#pragma unroll
    for (int i = 0; i < 4; i++) {
        int n = n0 + ty + 8 * i;
        float v = t[tx][ty + 8 * i];
        __nv_bfloat16 h = __float2bfloat16(v);
        th[(size_t)n * K + k0 + tx] = h;
        tl[(size_t)n * K + k0 + tx] = __float2bfloat16(v - __bfloat162float(h));
    }
}

// ------------------------------------ RoPE ----------------------------------
__global__ void rope_kernel() {
    int idx = blockIdx.x * blockDim.x + threadIdx.x;
    const int half_total = BB * NH * SS * (DK / 2);
    float* arr = (idx < half_total) ? g_q : g_k;
    int p = idx & (half_total - 1);
    int d2 = p & 31;
    int s = (p >> 5) & (SS - 1);
    int bh = p >> 16;
    int off = (bh * SS + s) * DK + 2 * d2;
    float inv = powf(10000.0f, -(float)d2 * (1.0f / 32.0f));
    float ang = (float)s * inv;
    float c = cosf(ang);
    float si = sinf(ang);
    float e = arr[off];
    float o = arr[off + 1];
    arr[off]     = e * c - o * si;
    arr[off + 1] = o * c + e * si;
}

// ------------------------- sliding-window attention -------------------------
#define AT_STR 65
#define AT_SMEM_FLOATS (3 * 64 * AT_STR)

__global__ __launch_bounds__(256) void attn_kernel() {
    extern __shared__ float sm[];
    float* Qs  = sm;
    float* KsP = sm + 64 * AT_STR;
    float* Vs  = sm + 2 * 64 * AT_STR;

    int tid = threadIdx.x;
    int ty = tid >> 4, tx = tid & 15;
    int q0 = blockIdx.x * 64;
    int hh = blockIdx.y;
    int b = blockIdx.z;

    const float* Qg = g_q + (size_t)((b * NH + hh) * SS) * DK;
    const float* Kg = g_k + (size_t)((b * NH + hh) * SS) * DK;
    const float* Vg = g_v + (size_t)((b * NH + hh) * SS) * DK;

#pragma unroll
    for (int it = 0; it < 4; it++) {
        int f = tid + it * 256;
        int r = f >> 4, c4 = f & 15;
        float4 v = *(const float4*)&Qg[(q0 + r) * DK + c4 * 4];
        Qs[r * AT_STR + c4 * 4 + 0] = v.x;
        Qs[r * AT_STR + c4 * 4 + 1] = v.y;
        Qs[r * AT_STR + c4 * 4 + 2] = v.z;
        Qs[r * AT_STR + c4 * 4 + 3] = v.w;
    }

    float acc[4][4];
    float mrow[4], lrow[4];
#pragma unroll
    for (int i = 0; i < 4; i++) {
        mrow[i] = -1e30f;
        lrow[i] = 0.f;
#pragma unroll
        for (int j = 0; j < 4; j++) acc[i][j] = 0.f;
    }

    int first = (q0 >= WIN) ? (q0 - WIN) : 0;
    int ntiles = (q0 + 63 - first) / 64 + 1;

    for (int t = 0; t < ntiles; t++) {
        int k0 = first + t * 64;
        __syncthreads();
#pragma unroll
        for (int it = 0; it < 4; it++) {
            int f = tid + it * 256;
            int r = f >> 4, c4 = f & 15;
            float4 kv = *(const float4*)&Kg[(k0 + r) * DK + c4 * 4];
            KsP[r * AT_STR + c4 * 4 + 0] = kv.x;
            KsP[r * AT_STR + c4 * 4 + 1] = kv.y;
            KsP[r * AT_STR + c4 * 4 + 2] = kv.z;
            KsP[r * AT_STR + c4 * 4 + 3] = kv.w;
            float4 vv = *(const float4*)&Vg[(k0 + r) * DK + c4 * 4];
            Vs[r * AT_STR + c4 * 4 + 0] = vv.x;
            Vs[r * AT_STR + c4 * 4 + 1] = vv.y;
            Vs[r * AT_STR + c4 * 4 + 2] = vv.z;
            Vs[r * AT_STR + c4 * 4 + 3] = vv.w;
        }
        __syncthreads();

        float sreg[4][4];
#pragma unroll
        for (int i = 0; i < 4; i++)
#pragma unroll
            for (int j = 0; j < 4; j++) sreg[i][j] = 0.f;
#pragma unroll 8
        for (int d = 0; d < 64; d++) {
            float qa[4], kb[4];
#pragma unroll
            for (int i = 0; i < 4; i++) qa[i] = Qs[(ty + 16 * i) * AT_STR + d];
#pragma unroll
            for (int j = 0; j < 4; j++) kb[j] = KsP[(tx + 16 * j) * AT_STR + d];
#pragma unroll
            for (int i = 0; i < 4; i++)
#pragma unroll
                for (int j = 0; j < 4; j++) sreg[i][j] += qa[i] * kb[j];
        }
#pragma unroll
        for (int i = 0; i < 4; i++) {
            int iq = q0 + ty + 16 * i;
#pragma unroll
            for (int j = 0; j < 4; j++) {
                int jk = k0 + tx + 16 * j;
                bool ok = (jk <= iq) && (jk >= iq - WIN);
                sreg[i][j] = ok ? sreg[i][j] * 0.125f : -1e30f;
            }
        }

        float corr[4];
#pragma unroll
        for (int i = 0; i < 4; i++) {
            float tmax = fmaxf(fmaxf(sreg[i][0], sreg[i][1]),
                               fmaxf(sreg[i][2], sreg[i][3]));
#pragma unroll
            for (int off = 8; off >= 1; off >>= 1)
                tmax = fmaxf(tmax, __shfl_xor_sync(0xffffffffu, tmax, off, 16));
            float mn = fmaxf(mrow[i], tmax);
            corr[i] = __expf(mrow[i] - mn);
            mrow[i] = mn;
        }

        __syncthreads();
#pragma unroll
        for (int i = 0; i < 4; i++) {
            float psum = 0.f;
#pragma unroll
            for (int j = 0; j < 4; j++) {
                float p = __expf(sreg[i][j] - mrow[i]);
                KsP[(ty + 16 * i) * AT_STR + tx + 16 * j] = p;
                psum += p;
                acc[i][j] *= corr[i];
            }
#pragma unroll
            for (int off = 8; off >= 1; off >>= 1)
                psum += __shfl_xor_sync(0xffffffffu, psum, off, 16);
            lrow[i] = lrow[i] * corr[i] + psum;
        }
        __syncthreads();

#pragma unroll 8
        for (int k = 0; k < 64; k++) {
            float pa[4], vb[4];
#pragma unroll
            for (int i = 0; i < 4; i++) pa[i] = KsP[(ty + 16 * i) * AT_STR + k];
#pragma unroll
            for (int j = 0; j < 4; j++) vb[j] = Vs[k * AT_STR + tx + 16 * j];
#pragma unroll
            for (int i = 0; i < 4; i++)
#pragma unroll
                for (int j = 0; j < 4; j++) acc[i][j] += pa[i] * vb[j];
        }
    }

    // epilogue: bf16 hi/lo split of attention output (feeds mma_gemm_out)
#pragma unroll
    for (int i = 0; i < 4; i++) {
        int s = q0 + ty + 16 * i;
        float inv_l = 1.0f / lrow[i];
#pragma unroll
        for (int j = 0; j < 4; j++) {
            size_t off = (size_t)(b * SS + s) * DM + hh * DK + tx + 16 * j;
            float o = acc[i][j] * inv_l;
            __nv_bfloat16 h = __float2bfloat16(o);
            g_at_hi[off] = h;
            g_at_lo[off] = __float2bfloat16(o - __bfloat162float(h));
        }
    }
}

// ---------------------------------------------------------------------------

extern "C" void kernel_launch(void* const* d_in, const int* in_sizes, int n_in,
                              void* d_out, int out_size) {
    const float* x     = (const float*)d_in[0];
    const float* w_qkv = (const float*)d_in[1];
    const float* w_o   = (const float*)d_in[2];
    float* out = (float*)d_out;

    cudaFuncSetAttribute(attn_kernel, cudaFuncAttributeMaxDynamicSharedMemorySize,
                         AT_SMEM_FLOATS * (int)sizeof(float));

    // 0) fp32 -> bf16 hi/lo splits (outputs are device globals, device-side)
    conv_split<<<(BB * SS * DM) / (256 * 4), 256>>>(x);
    conv_wT<<<dim3(3 * DM / 32, DM / 32), dim3(32, 8)>>>(w_qkv, 0, DM, 3 * DM);
    conv_wT<<<dim3(DM / 32, DM / 32), dim3(32, 8)>>>(w_o, 1, DM, DM);

    // 1) QKV projection on HMMA (bf16x3), scatter into g_q/g_k/g_v
    mma_gemm_qkv<<<dim3(3 * DM / 128, BB * SS / 128), 256>>>();

    // 2) RoPE
    rope_kernel<<<(2 * BB * NH * SS * (DK / 2)) / 256, 256>>>();

    // 3) sliding-window attention (writes bf16 hi/lo directly)
    attn_kernel<<<dim3(SS / 64, NH, BB), 256, AT_SMEM_FLOATS * sizeof(float)>>>();

    // 4) output projection on HMMA
    mma_gemm_out<<<dim3(DM / 128, BB * SS / 128), 256>>>(out);
}

// round 14
// speedup vs baseline: 1.9585x; 1.1399x over previous
#include <cuda_runtime.h>
#include <cuda_bf16.h>
#include <cstdint>

#define BB 2
#define SS 2048
#define DM 1024
#define NH 16
#define DK 64
#define WIN 512

// ------------------------- scratch (device globals) -------------------------
__device__ float g_q[BB*NH*SS*DK];
__device__ float g_k[BB*NH*SS*DK];
__device__ float g_v[BB*NH*SS*DK];
__device__ __align__(256) __nv_bfloat16 g_x_hi[BB*SS*DM];
__device__ __align__(256) __nv_bfloat16 g_x_lo[BB*SS*DM];
__device__ __align__(256) __nv_bfloat16 g_wq_hi[3*DM*DM];
__device__ __align__(256) __nv_bfloat16 g_wq_lo[3*DM*DM];
__device__ __align__(256) __nv_bfloat16 g_wo_hi[DM*DM];
__device__ __align__(256) __nv_bfloat16 g_wo_lo[DM*DM];
__device__ __align__(256) __nv_bfloat16 g_at_hi[BB*SS*DM];
__device__ __align__(256) __nv_bfloat16 g_at_lo[BB*SS*DM];

// ------------------------------ helpers -------------------------------------
__device__ __forceinline__ uint32_t smem_u32(const void* p) {
    uint32_t a;
    asm("{ .reg .u64 t; cvta.to.shared.u64 t, %1; cvt.u32.u64 %0, t; }"
        : "=r"(a) : "l"(p));
    return a;
}
__device__ __forceinline__ void cp_async16(uint32_t dst, const void* src) {
    asm volatile("cp.async.cg.shared.global [%0], [%1], 16;"
                 :: "r"(dst), "l"(src));
}
__device__ __forceinline__ void cp_commit() {
    asm volatile("cp.async.commit_group;" ::: "memory");
}
__device__ __forceinline__ void mma_bf16(float* d, const uint32_t* a,
                                         const uint32_t* b) {
    asm volatile(
        "mma.sync.aligned.m16n8k16.row.col.f32.bf16.bf16.f32 "
        "{%0,%1,%2,%3}, {%4,%5,%6,%7}, {%8,%9}, {%0,%1,%2,%3};"
        : "+f"(d[0]), "+f"(d[1]), "+f"(d[2]), "+f"(d[3])
        : "r"(a[0]), "r"(a[1]), "r"(a[2]), "r"(a[3]), "r"(b[0]), "r"(b[1]));
}

// ------------- bf16x3 HMMA GEMM mainloop: 128x128 CTA, K=1024 ---------------
// 3-stage cp.async pipeline. Each stage: 4 tiles (Ah, Al, Bh, Bl),
// 128 rows x 32 bf16, row stride 40 (bank = 20*q + c -> conflict-free).
// Fragments via plain LDS.32 at PTX m16n8k16 fragment coordinates (verified).
#define MM_STR 40
#define MM_TILE (128 * MM_STR)                      // elements per tile
#define MM_STAGE (4 * MM_TILE)                      // elements per stage
#define MM_NCHUNK 32
#define MM_SMEM_BYTES (3 * MM_STAGE * 2)            // 122880 bytes

__device__ __forceinline__ void mm_issue(
    __nv_bfloat16* stage, int tid,
    const __nv_bfloat16* __restrict__ Ah, const __nv_bfloat16* __restrict__ Al,
    const __nv_bfloat16* __restrict__ Bh, const __nv_bfloat16* __restrict__ Bl,
    int m0, int n0, int t)
{
#pragma unroll
    for (int tile = 0; tile < 4; tile++) {
        const __nv_bfloat16* src;
        int rb;
        if      (tile == 0) { src = Ah; rb = m0; }
        else if (tile == 1) { src = Al; rb = m0; }
        else if (tile == 2) { src = Bh; rb = n0; }
        else                { src = Bl; rb = n0; }
        __nv_bfloat16* dst = stage + tile * MM_TILE;
#pragma unroll
        for (int it = 0; it < 2; it++) {
            int idx = tid + it * 256;
            int r = idx >> 2, c = idx & 3;
            cp_async16(smem_u32(dst + r * MM_STR + c * 8),
                       src + (size_t)(rb + r) * DM + t * 32 + c * 8);
        }
    }
    cp_commit();
}

__device__ __forceinline__ void mma_mainloop(
    __nv_bfloat16* sm,
    const __nv_bfloat16* __restrict__ Ah, const __nv_bfloat16* __restrict__ Al,
    const __nv_bfloat16* __restrict__ Bh, const __nv_bfloat16* __restrict__ Bl,
    int m0, int n0, float acc[4][4][4])
{
    int tid = threadIdx.x;
    int wid = tid >> 5, lane = tid & 31;
    int wm = wid & 1, wn = wid >> 1;        // warp tile: rows wm*64, cols wn*32
    int qr = lane >> 2;                     // 0..7
    int qc = (lane & 3) * 2;                // 0,2,4,6

#pragma unroll
    for (int mi = 0; mi < 4; mi++)
#pragma unroll
        for (int ni = 0; ni < 4; ni++)
#pragma unroll
            for (int k = 0; k < 4; k++) acc[mi][ni][k] = 0.f;

    // prologue: stages 0 and 1 in flight
    mm_issue(sm,            tid, Ah, Al, Bh, Bl, m0, n0, 0);
    mm_issue(sm + MM_STAGE, tid, Ah, Al, Bh, Bl, m0, n0, 1);

    for (int t = 0; t < MM_NCHUNK; t++) {
        if (t + 1 < MM_NCHUNK)
            asm volatile("cp.async.wait_group 1;" ::: "memory");
        else
            asm volatile("cp.async.wait_group 0;" ::: "memory");
        __syncthreads();   // chunk t visible to all; all reads of stage (t+2)%3 done

        const __nv_bfloat16* st = sm + (t % 3) * MM_STAGE;
        const __nv_bfloat16* At0 = st;                 // Ah
        const __nv_bfloat16* At1 = st + MM_TILE;       // Al
        const __nv_bfloat16* Bt0 = st + 2 * MM_TILE;   // Bh
        const __nv_bfloat16* Bt1 = st + 3 * MM_TILE;   // Bl

#pragma unroll
        for (int kk = 0; kk < 2; kk++) {               // k16 steps
            int kc = kk * 16 + qc;
            uint32_t ah[4][4], al[4][4], bh[4][2], bl[4][2];
#pragma unroll
            for (int mi = 0; mi < 4; mi++) {
                int row = wm * 64 + mi * 16 + qr;
                ah[mi][0] = *(const uint32_t*)(At0 + row * MM_STR + kc);
                ah[mi][1] = *(const uint32_t*)(At0 + (row + 8) * MM_STR + kc);
                ah[mi][2] = *(const uint32_t*)(At0 + row * MM_STR + kc + 8);
                ah[mi][3] = *(const uint32_t*)(At0 + (row + 8) * MM_STR + kc + 8);
                al[mi][0] = *(const uint32_t*)(At1 + row * MM_STR + kc);
                al[mi][1] = *(const uint32_t*)(At1 + (row + 8) * MM_STR + kc);
                al[mi][2] = *(const uint32_t*)(At1 + row * MM_STR + kc + 8);
                al[mi][3] = *(const uint32_t*)(At1 + (row + 8) * MM_STR + kc + 8);
            }
#pragma unroll
            for (int ni = 0; ni < 4; ni++) {
                int brow = wn * 32 + ni * 8 + qr;
                bh[ni][0] = *(const uint32_t*)(Bt0 + brow * MM_STR + kc);
                bh[ni][1] = *(const uint32_t*)(Bt0 + brow * MM_STR + kc + 8);
                bl[ni][0] = *(const uint32_t*)(Bt1 + brow * MM_STR + kc);
                bl[ni][1] = *(const uint32_t*)(Bt1 + brow * MM_STR + kc + 8);
            }
#pragma unroll
            for (int mi = 0; mi < 4; mi++)
#pragma unroll
                for (int ni = 0; ni < 4; ni++) {
                    mma_bf16(acc[mi][ni], ah[mi], bh[ni]);  // Ah*Bh
                    mma_bf16(acc[mi][ni], ah[mi], bl[ni]);  // Ah*Bl
                    mma_bf16(acc[mi][ni], al[mi], bh[ni]);  // Al*Bh
                }
        }

        if (t + 2 < MM_NCHUNK)
            mm_issue(sm + ((t + 2) % 3) * MM_STAGE, tid,
                     Ah, Al, Bh, Bl, m0, n0, t + 2);
    }
}

// ---------------------------- QKV projection GEMM ---------------------------
__global__ __launch_bounds__(256) void mma_gemm_qkv() {
    extern __shared__ __nv_bfloat16 smem[];
    int m0 = blockIdx.y * 128, n0 = blockIdx.x * 128;
    float acc[4][4][4];
    mma_mainloop(smem, g_x_hi, g_x_lo, g_wq_hi, g_wq_lo, m0, n0, acc);

    int tid = threadIdx.x, wid = tid >> 5, lane = tid & 31;
    int wm = wid & 1, wn = wid >> 1;
    int g = lane >> 2, tt = lane & 3;

    int ncol = n0 + wn * 32;                 // warp col base (32-aligned)
    int part = n0 >> 10;                     // q/k/v (uniform per block)
    int hh = (ncol & 1023) >> 6;             // head (uniform per warp)
    int d0 = ncol & 63;                      // 0 or 32
    float* dst = (part == 0) ? g_q : ((part == 1) ? g_k : g_v);

#pragma unroll
    for (int mi = 0; mi < 4; mi++) {
#pragma unroll
        for (int half = 0; half < 2; half++) {
            int m = m0 + wm * 64 + mi * 16 + g + half * 8;
            int b = m >> 11, s = m & (SS - 1);
            float* p = dst + ((size_t)((b * NH + hh) * SS + s)) * DK;
#pragma unroll
            for (int ni = 0; ni < 4; ni++) {
                float2 v;
                v.x = acc[mi][ni][half * 2 + 0];
                v.y = acc[mi][ni][half * 2 + 1];
                *(float2*)(p + d0 + ni * 8 + tt * 2) = v;
            }
        }
    }
}

// ------------------------------- output GEMM --------------------------------
__global__ __launch_bounds__(256) void mma_gemm_out(float* __restrict__ C) {
    extern __shared__ __nv_bfloat16 smem[];
    int m0 = blockIdx.y * 128, n0 = blockIdx.x * 128;
    float acc[4][4][4];
    mma_mainloop(smem, g_at_hi, g_at_lo, g_wo_hi, g_wo_lo, m0, n0, acc);

    int tid = threadIdx.x, wid = tid >> 5, lane = tid & 31;
    int wm = wid & 1, wn = wid >> 1;
    int g = lane >> 2, tt = lane & 3;
#pragma unroll
    for (int mi = 0; mi < 4; mi++) {
#pragma unroll
        for (int half = 0; half < 2; half++) {
            int m = m0 + wm * 64 + mi * 16 + g + half * 8;
            float* p = C + (size_t)m * DM + n0 + wn * 32;
#pragma unroll
            for (int ni = 0; ni < 4; ni++) {
                float2 v;
                v.x = acc[mi][ni][half * 2 + 0];
                v.y = acc[mi][ni][half * 2 + 1];
                *(float2*)(p + ni * 8 + tt * 2) = v;
            }
        }
    }
}

// ------------------------- convert / transpose kernels ----------------------
// Device globals referenced ONLY inside device code (never as host-passed args).
__global__ void conv_split(const float* __restrict__ s) {
    int i = (blockIdx.x * 256 + threadIdx.x) * 4;
    __nv_bfloat16* hi = g_x_hi;
    __nv_bfloat16* lo = g_x_lo;
    float4 v = *(const float4*)(s + i);
    __nv_bfloat16 h0 = __float2bfloat16(v.x), h1 = __float2bfloat16(v.y);
    __nv_bfloat16 h2 = __float2bfloat16(v.z), h3 = __float2bfloat16(v.w);
    __nv_bfloat162 H0; H0.x = h0; H0.y = h1;
    __nv_bfloat162 H1; H1.x = h2; H1.y = h3;
    *(__nv_bfloat162*)(hi + i)     = H0;
    *(__nv_bfloat162*)(hi + i + 2) = H1;
    __nv_bfloat162 L0, L1;
    L0.x = __float2bfloat16(v.x - __bfloat162float(h0));
    L0.y = __float2bfloat16(v.y - __bfloat162float(h1));
    L1.x = __float2bfloat16(v.z - __bfloat162float(h2));
    L1.y = __float2bfloat16(v.w - __bfloat162float(h3));
    *(__nv_bfloat162*)(lo + i)     = L0;
    *(__nv_bfloat162*)(lo + i + 2) = L1;
}

__global__ void conv_wT(const float* __restrict__ w, int which, int K, int N) {
    __nv_bfloat16* th = which ? g_wo_hi : g_wq_hi;
    __nv_bfloat16* tl = which ? g_wo_lo : g_wq_lo;
    __shared__ float t[32][33];
    int n0 = blockIdx.x * 32, k0 = blockIdx.y * 32;
    int tx = threadIdx.x, ty = threadIdx.y;
#pragma unroll
    for (int i = 0; i < 4; i++)
        t[ty + 8 * i][tx] = w[(size_t)(k0 + ty + 8 * i) * N + n0 + tx];
    __syncthreads();
#pragma unroll
    for (int i = 0; i < 4; i++) {
        int n = n0 + ty + 8 * i;
        float v = t[tx][ty + 8 * i];
        __nv_bfloat16 h = __float2bfloat16(v);
        th[(size_t)n * K + k0 + tx] = h;
        tl[(size_t)n * K + k0 + tx] = __float2bfloat16(v - __bfloat162float(h));
    }
}

// ------------------------------------ RoPE ----------------------------------
__global__ void rope_kernel() {
    int idx = blockIdx.x * blockDim.x + threadIdx.x;
    const int half_total = BB * NH * SS * (DK / 2);
    float* arr = (idx < half_total) ? g_q : g_k;
    int p = idx & (half_total - 1);
    int d2 = p & 31;
    int s = (p >> 5) & (SS - 1);
    int bh = p >> 16;
    int off = (bh * SS + s) * DK + 2 * d2;
    float inv = powf(10000.0f, -(float)d2 * (1.0f / 32.0f));
    float ang = (float)s * inv;
    float c = cosf(ang);
    float si = sinf(ang);
    float e = arr[off];
    float o = arr[off + 1];
    arr[off]     = e * c - o * si;
    arr[off + 1] = o * c + e * si;
}

// ------------------------- sliding-window attention -------------------------
#define AT_STR 65
#define AT_SMEM_FLOATS (3 * 64 * AT_STR)

__global__ __launch_bounds__(256) void attn_kernel() {
    extern __shared__ float sm[];
    float* Qs  = sm;
    float* KsP = sm + 64 * AT_STR;
    float* Vs  = sm + 2 * 64 * AT_STR;

    int tid = threadIdx.x;
    int ty = tid >> 4, tx = tid & 15;
    int q0 = blockIdx.x * 64;
    int hh = blockIdx.y;
    int b = blockIdx.z;

    const float* Qg = g_q + (size_t)((b * NH + hh) * SS) * DK;
    const float* Kg = g_k + (size_t)((b * NH + hh) * SS) * DK;
    const float* Vg = g_v + (size_t)((b * NH + hh) * SS) * DK;

#pragma unroll
    for (int it = 0; it < 4; it++) {
        int f = tid + it * 256;
        int r = f >> 4, c4 = f & 15;
        float4 v = *(const float4*)&Qg[(q0 + r) * DK + c4 * 4];
        Qs[r * AT_STR + c4 * 4 + 0] = v.x;
        Qs[r * AT_STR + c4 * 4 + 1] = v.y;
        Qs[r * AT_STR + c4 * 4 + 2] = v.z;
        Qs[r * AT_STR + c4 * 4 + 3] = v.w;
    }

    float acc[4][4];
    float mrow[4], lrow[4];
#pragma unroll
    for (int i = 0; i < 4; i++) {
        mrow[i] = -1e30f;
        lrow[i] = 0.f;
#pragma unroll
        for (int j = 0; j < 4; j++) acc[i][j] = 0.f;
    }

    int first = (q0 >= WIN) ? (q0 - WIN) : 0;
    int ntiles = (q0 + 63 - first) / 64 + 1;

    for (int t = 0; t < ntiles; t++) {
        int k0 = first + t * 64;
        __syncthreads();
#pragma unroll
        for (int it = 0; it < 4; it++) {
            int f = tid + it * 256;
            int r = f >> 4, c4 = f & 15;
            float4 kv = *(const float4*)&Kg[(k0 + r) * DK + c4 * 4];
            KsP[r * AT_STR + c4 * 4 + 0] = kv.x;
            KsP[r * AT_STR + c4 * 4 + 1] = kv.y;
            KsP[r * AT_STR + c4 * 4 + 2] = kv.z;
            KsP[r * AT_STR + c4 * 4 + 3] = kv.w;
            float4 vv = *(const float4*)&Vg[(k0 + r) * DK + c4 * 4];
            Vs[r * AT_STR + c4 * 4 + 0] = vv.x;
            Vs[r * AT_STR + c4 * 4 + 1] = vv.y;
            Vs[r * AT_STR + c4 * 4 + 2] = vv.z;
            Vs[r * AT_STR + c4 * 4 + 3] = vv.w;
        }
        __syncthreads();

        float sreg[4][4];
#pragma unroll
        for (int i = 0; i < 4; i++)
#pragma unroll
            for (int j = 0; j < 4; j++) sreg[i][j] = 0.f;
#pragma unroll 8
        for (int d = 0; d < 64; d++) {
            float qa[4], kb[4];
#pragma unroll
            for (int i = 0; i < 4; i++) qa[i] = Qs[(ty + 16 * i) * AT_STR + d];
#pragma unroll
            for (int j = 0; j < 4; j++) kb[j] = KsP[(tx + 16 * j) * AT_STR + d];
#pragma unroll
            for (int i = 0; i < 4; i++)
#pragma unroll
                for (int j = 0; j < 4; j++) sreg[i][j] += qa[i] * kb[j];
        }
#pragma unroll
        for (int i = 0; i < 4; i++) {
            int iq = q0 + ty + 16 * i;
#pragma unroll
            for (int j = 0; j < 4; j++) {
                int jk = k0 + tx + 16 * j;
                bool ok = (jk <= iq) && (jk >= iq - WIN);
                sreg[i][j] = ok ? sreg[i][j] * 0.125f : -1e30f;
            }
        }

        float corr[4];
#pragma unroll
        for (int i = 0; i < 4; i++) {
            float tmax = fmaxf(fmaxf(sreg[i][0], sreg[i][1]),
                               fmaxf(sreg[i][2], sreg[i][3]));
#pragma unroll
            for (int off = 8; off >= 1; off >>= 1)
                tmax = fmaxf(tmax, __shfl_xor_sync(0xffffffffu, tmax, off, 16));
            float mn = fmaxf(mrow[i], tmax);
            corr[i] = __expf(mrow[i] - mn);
            mrow[i] = mn;
        }

        __syncthreads();
#pragma unroll
        for (int i = 0; i < 4; i++) {
            float psum = 0.f;
#pragma unroll
            for (int j = 0; j < 4; j++) {
                float p = __expf(sreg[i][j] - mrow[i]);
                KsP[(ty + 16 * i) * AT_STR + tx + 16 * j] = p;
                psum += p;
                acc[i][j] *= corr[i];
            }
#pragma unroll
            for (int off = 8; off >= 1; off >>= 1)
                psum += __shfl_xor_sync(0xffffffffu, psum, off, 16);
            lrow[i] = lrow[i] * corr[i] + psum;
        }
        __syncthreads();

#pragma unroll 8
        for (int k = 0; k < 64; k++) {
            float pa[4], vb[4];
#pragma unroll
            for (int i = 0; i < 4; i++) pa[i] = KsP[(ty + 16 * i) * AT_STR + k];
#pragma unroll
            for (int j = 0; j < 4; j++) vb[j] = Vs[k * AT_STR + tx + 16 * j];
#pragma unroll
            for (int i = 0; i < 4; i++)
#pragma unroll
                for (int j = 0; j < 4; j++) acc[i][j] += pa[i] * vb[j];
        }
    }

    // epilogue: bf16 hi/lo split of attention output (feeds mma_gemm_out)
#pragma unroll
    for (int i = 0; i < 4; i++) {
        int s = q0 + ty + 16 * i;
        float inv_l = 1.0f / lrow[i];
#pragma unroll
        for (int j = 0; j < 4; j++) {
            size_t off = (size_t)(b * SS + s) * DM + hh * DK + tx + 16 * j;
            float o = acc[i][j] * inv_l;
            __nv_bfloat16 h = __float2bfloat16(o);
            g_at_hi[off] = h;
            g_at_lo[off] = __float2bfloat16(o - __bfloat162float(h));
        }
    }
}

// ---------------------------------------------------------------------------

extern "C" void kernel_launch(void* const* d_in, const int* in_sizes, int n_in,
                              void* d_out, int out_size) {
    const float* x     = (const float*)d_in[0];
    const float* w_qkv = (const float*)d_in[1];
    const float* w_o   = (const float*)d_in[2];
    float* out = (float*)d_out;

    cudaFuncSetAttribute(mma_gemm_qkv, cudaFuncAttributeMaxDynamicSharedMemorySize,
                         MM_SMEM_BYTES);
    cudaFuncSetAttribute(mma_gemm_out, cudaFuncAttributeMaxDynamicSharedMemorySize,
                         MM_SMEM_BYTES);
    cudaFuncSetAttribute(attn_kernel, cudaFuncAttributeMaxDynamicSharedMemorySize,
                         AT_SMEM_FLOATS * (int)sizeof(float));

    // 0) fp32 -> bf16 hi/lo splits (outputs are device globals, device-side)
    conv_split<<<(BB * SS * DM) / (256 * 4), 256>>>(x);
    conv_wT<<<dim3(3 * DM / 32, DM / 32), dim3(32, 8)>>>(w_qkv, 0, DM, 3 * DM);
    conv_wT<<<dim3(DM / 32, DM / 32), dim3(32, 8)>>>(w_o, 1, DM, DM);

    // 1) QKV projection on HMMA (bf16x3, cp.async pipelined)
    mma_gemm_qkv<<<dim3(3 * DM / 128, BB * SS / 128), 256, MM_SMEM_BYTES>>>();

    // 2) RoPE
    rope_kernel<<<(2 * BB * NH * SS * (DK / 2)) / 256, 256>>>();

    // 3) sliding-window attention (writes bf16 hi/lo directly)
    attn_kernel<<<dim3(SS / 64, NH, BB), 256, AT_SMEM_FLOATS * sizeof(float)>>>();

    // 4) output projection on HMMA
    mma_gemm_out<<<dim3(DM / 128, BB * SS / 128), 256, MM_SMEM_BYTES>>>(out);
}

// round 17
// speedup vs baseline: 2.8544x; 1.4574x over previous
#include <cuda_runtime.h>
#include <cuda_bf16.h>
#include <cuda_fp16.h>
#include <cstdint>

#define BB 2
#define SS 2048
#define DM 1024
#define NH 16
#define DK 64
#define WIN 512

// ------------------------- scratch (device globals) -------------------------
__device__ float g_q[BB*NH*SS*DK];
__device__ float g_k[BB*NH*SS*DK];
__device__ float g_v[BB*NH*SS*DK];
__device__ __align__(256) __nv_bfloat16 g_x_hi[BB*SS*DM];
__device__ __align__(256) __nv_bfloat16 g_x_lo[BB*SS*DM];
__device__ __align__(256) __nv_bfloat16 g_wq_hi[3*DM*DM];
__device__ __align__(256) __nv_bfloat16 g_wq_lo[3*DM*DM];
__device__ __align__(256) __nv_bfloat16 g_wo_hi[DM*DM];
__device__ __align__(256) __nv_bfloat16 g_wo_lo[DM*DM];
__device__ __align__(256) __nv_bfloat16 g_at_hi[BB*SS*DM];
__device__ __align__(256) __nv_bfloat16 g_at_lo[BB*SS*DM];
// attention operands (bf16 split q/k after rope, fp16 split V^T)
__device__ __align__(256) __nv_bfloat16 g_qh[BB*NH*SS*DK];
__device__ __align__(256) __nv_bfloat16 g_ql[BB*NH*SS*DK];
__device__ __align__(256) __nv_bfloat16 g_kh[BB*NH*SS*DK];
__device__ __align__(256) __nv_bfloat16 g_kl[BB*NH*SS*DK];
__device__ __align__(256) __half        g_vth[BB*NH*DK*SS];
__device__ __align__(256) __half        g_vtl[BB*NH*DK*SS];

// ------------------------------ helpers -------------------------------------
__device__ __forceinline__ uint32_t smem_u32(const void* p) {
    uint32_t a;
    asm("{ .reg .u64 t; cvta.to.shared.u64 t, %1; cvt.u32.u64 %0, t; }"
        : "=r"(a) : "l"(p));
    return a;
}
__device__ __forceinline__ void cp_async16(uint32_t dst, const void* src) {
    asm volatile("cp.async.cg.shared.global [%0], [%1], 16;"
                 :: "r"(dst), "l"(src));
}
__device__ __forceinline__ void cp_commit() {
    asm volatile("cp.async.commit_group;" ::: "memory");
}
__device__ __forceinline__ void mma_bf16(float* d, const uint32_t* a,
                                         const uint32_t* b) {
    asm volatile(
        "mma.sync.aligned.m16n8k16.row.col.f32.bf16.bf16.f32 "
        "{%0,%1,%2,%3}, {%4,%5,%6,%7}, {%8,%9}, {%0,%1,%2,%3};"
        : "+f"(d[0]), "+f"(d[1]), "+f"(d[2]), "+f"(d[3])
        : "r"(a[0]), "r"(a[1]), "r"(a[2]), "r"(a[3]), "r"(b[0]), "r"(b[1]));
}
__device__ __forceinline__ void mma_f16(float* d, const uint32_t* a,
                                        const uint32_t* b) {
    asm volatile(
        "mma.sync.aligned.m16n8k16.row.col.f32.f16.f16.f32 "
        "{%0,%1,%2,%3}, {%4,%5,%6,%7}, {%8,%9}, {%0,%1,%2,%3};"
        : "+f"(d[0]), "+f"(d[1]), "+f"(d[2]), "+f"(d[3])
        : "r"(a[0]), "r"(a[1]), "r"(a[2]), "r"(a[3]), "r"(b[0]), "r"(b[1]));
}
__device__ __forceinline__ uint32_t pack_h2(float lo, float hi) {
    __half2 h = __floats2half2_rn(lo, hi);   // x=lo (low 16b), y=hi
    return *(uint32_t*)&h;
}

// ------------- bf16x3 HMMA GEMM mainloop: 128x128 CTA, K=1024 ---------------
// 2-stage cp.async double buffer -> 80KB smem -> 2 CTAs/SM.
#define MM_STR 40
#define MM_TILE (128 * MM_STR)
#define MM_STAGE (4 * MM_TILE)
#define MM_NCHUNK 32
#define MM_SMEM_BYTES (2 * MM_STAGE * 2)            // 81920 bytes

__device__ __forceinline__ void mm_issue(
    __nv_bfloat16* stage, int tid,
    const __nv_bfloat16* __restrict__ Ah, const __nv_bfloat16* __restrict__ Al,
    const __nv_bfloat16* __restrict__ Bh, const __nv_bfloat16* __restrict__ Bl,
    int m0, int n0, int t)
{
#pragma unroll
    for (int tile = 0; tile < 4; tile++) {
        const __nv_bfloat16* src;
        int rb;
        if      (tile == 0) { src = Ah; rb = m0; }
        else if (tile == 1) { src = Al; rb = m0; }
        else if (tile == 2) { src = Bh; rb = n0; }
        else                { src = Bl; rb = n0; }
        __nv_bfloat16* dst = stage + tile * MM_TILE;
#pragma unroll
        for (int it = 0; it < 2; it++) {
            int idx = tid + it * 256;
            int r = idx >> 2, c = idx & 3;
            cp_async16(smem_u32(dst + r * MM_STR + c * 8),
                       src + (size_t)(rb + r) * DM + t * 32 + c * 8);
        }
    }
    cp_commit();
}

__device__ __forceinline__ void mma_mainloop(
    __nv_bfloat16* sm,
    const __nv_bfloat16* __restrict__ Ah, const __nv_bfloat16* __restrict__ Al,
    const __nv_bfloat16* __restrict__ Bh, const __nv_bfloat16* __restrict__ Bl,
    int m0, int n0, float acc[4][4][4])
{
    int tid = threadIdx.x;
    int wid = tid >> 5, lane = tid & 31;
    int wm = wid & 1, wn = wid >> 1;
    int qr = lane >> 2;
    int qc = (lane & 3) * 2;

#pragma unroll
    for (int mi = 0; mi < 4; mi++)
#pragma unroll
        for (int ni = 0; ni < 4; ni++)
#pragma unroll
            for (int k = 0; k < 4; k++) acc[mi][ni][k] = 0.f;

    mm_issue(sm, tid, Ah, Al, Bh, Bl, m0, n0, 0);

    for (int t = 0; t < MM_NCHUNK; t++) {
        asm volatile("cp.async.wait_group 0;" ::: "memory");
        __syncthreads();      // chunk t visible; all reads of other buffer done
        if (t + 1 < MM_NCHUNK)
            mm_issue(sm + ((t + 1) & 1) * MM_STAGE, tid,
                     Ah, Al, Bh, Bl, m0, n0, t + 1);

        const __nv_bfloat16* st = sm + (t & 1) * MM_STAGE;
        const __nv_bfloat16* At0 = st;
        const __nv_bfloat16* At1 = st + MM_TILE;
        const __nv_bfloat16* Bt0 = st + 2 * MM_TILE;
        const __nv_bfloat16* Bt1 = st + 3 * MM_TILE;

#pragma unroll
        for (int kk = 0; kk < 2; kk++) {
            int kc = kk * 16 + qc;
            uint32_t ah[4][4], al[4][4], bh[4][2], bl[4][2];
#pragma unroll
            for (int mi = 0; mi < 4; mi++) {
                int row = wm * 64 + mi * 16 + qr;
                ah[mi][0] = *(const uint32_t*)(At0 + row * MM_STR + kc);
                ah[mi][1] = *(const uint32_t*)(At0 + (row + 8) * MM_STR + kc);
                ah[mi][2] = *(const uint32_t*)(At0 + row * MM_STR + kc + 8);
                ah[mi][3] = *(const uint32_t*)(At0 + (row + 8) * MM_STR + kc + 8);
                al[mi][0] = *(const uint32_t*)(At1 + row * MM_STR + kc);
                al[mi][1] = *(const uint32_t*)(At1 + (row + 8) * MM_STR + kc);
                al[mi][2] = *(const uint32_t*)(At1 + row * MM_STR + kc + 8);
                al[mi][3] = *(const uint32_t*)(At1 + (row + 8) * MM_STR + kc + 8);
            }
#pragma unroll
            for (int ni = 0; ni < 4; ni++) {
                int brow = wn * 32 + ni * 8 + qr;
                bh[ni][0] = *(const uint32_t*)(Bt0 + brow * MM_STR + kc);
                bh[ni][1] = *(const uint32_t*)(Bt0 + brow * MM_STR + kc + 8);
                bl[ni][0] = *(const uint32_t*)(Bt1 + brow * MM_STR + kc);
                bl[ni][1] = *(const uint32_t*)(Bt1 + brow * MM_STR + kc + 8);
            }
#pragma unroll
            for (int mi = 0; mi < 4; mi++)
#pragma unroll
                for (int ni = 0; ni < 4; ni++) {
                    mma_bf16(acc[mi][ni], ah[mi], bh[ni]);
                    mma_bf16(acc[mi][ni], ah[mi], bl[ni]);
                    mma_bf16(acc[mi][ni], al[mi], bh[ni]);
                }
        }
    }
}

// ---------------------------- QKV projection GEMM ---------------------------
__global__ __launch_bounds__(256, 2) void mma_gemm_qkv() {
    extern __shared__ __nv_bfloat16 smem[];
    int m0 = blockIdx.y * 128, n0 = blockIdx.x * 128;
    float acc[4][4][4];
    mma_mainloop(smem, g_x_hi, g_x_lo, g_wq_hi, g_wq_lo, m0, n0, acc);

    int tid = threadIdx.x, wid = tid >> 5, lane = tid & 31;
    int wm = wid & 1, wn = wid >> 1;
    int g = lane >> 2, tt = lane & 3;

    int ncol = n0 + wn * 32;
    int part = n0 >> 10;
    int hh = (ncol & 1023) >> 6;
    int d0 = ncol & 63;
    float* dst = (part == 0) ? g_q : ((part == 1) ? g_k : g_v);

#pragma unroll
    for (int mi = 0; mi < 4; mi++) {
#pragma unroll
        for (int half = 0; half < 2; half++) {
            int m = m0 + wm * 64 + mi * 16 + g + half * 8;
            int b = m >> 11, s = m & (SS - 1);
            float* p = dst + ((size_t)((b * NH + hh) * SS + s)) * DK;
#pragma unroll
            for (int ni = 0; ni < 4; ni++) {
                float2 v;
                v.x = acc[mi][ni][half * 2 + 0];
                v.y = acc[mi][ni][half * 2 + 1];
                *(float2*)(p + d0 + ni * 8 + tt * 2) = v;
            }
        }
    }
}

// ------------------------------- output GEMM --------------------------------
__global__ __launch_bounds__(256, 2) void mma_gemm_out(float* __restrict__ C) {
    extern __shared__ __nv_bfloat16 smem[];
    int m0 = blockIdx.y * 128, n0 = blockIdx.x * 128;
    float acc[4][4][4];
    mma_mainloop(smem, g_at_hi, g_at_lo, g_wo_hi, g_wo_lo, m0, n0, acc);

    int tid = threadIdx.x, wid = tid >> 5, lane = tid & 31;
    int wm = wid & 1, wn = wid >> 1;
    int g = lane >> 2, tt = lane & 3;
#pragma unroll
    for (int mi = 0; mi < 4; mi++) {
#pragma unroll
        for (int half = 0; half < 2; half++) {
            int m = m0 + wm * 64 + mi * 16 + g + half * 8;
            float* p = C + (size_t)m * DM + n0 + wn * 32;
#pragma unroll
            for (int ni = 0; ni < 4; ni++) {
                float2 v;
                v.x = acc[mi][ni][half * 2 + 0];
                v.y = acc[mi][ni][half * 2 + 1];
                *(float2*)(p + ni * 8 + tt * 2) = v;
            }
        }
    }
}

// ------------------------- convert / transpose kernels ----------------------
__global__ void conv_split(const float* __restrict__ s) {
    int i = (blockIdx.x * 256 + threadIdx.x) * 4;
    __nv_bfloat16* hi = g_x_hi;
    __nv_bfloat16* lo = g_x_lo;
    float4 v = *(const float4*)(s + i);
    __nv_bfloat16 h0 = __float2bfloat16(v.x), h1 = __float2bfloat16(v.y);
    __nv_bfloat16 h2 = __float2bfloat16(v.z), h3 = __float2bfloat16(v.w);
    __nv_bfloat162 H0; H0.x = h0; H0.y = h1;
    __nv_bfloat162 H1; H1.x = h2; H1.y = h3;
    *(__nv_bfloat162*)(hi + i)     = H0;
    *(__nv_bfloat162*)(hi + i + 2) = H1;
    __nv_bfloat162 L0, L1;
    L0.x = __float2bfloat16(v.x - __bfloat162float(h0));
    L0.y = __float2bfloat16(v.y - __bfloat162float(h1));
    L1.x = __float2bfloat16(v.z - __bfloat162float(h2));
    L1.y = __float2bfloat16(v.w - __bfloat162float(h3));
    *(__nv_bfloat162*)(lo + i)     = L0;
    *(__nv_bfloat162*)(lo + i + 2) = L1;
}

__global__ void conv_wT(const float* __restrict__ w, int which, int K, int N) {
    __nv_bfloat16* th = which ? g_wo_hi : g_wq_hi;
    __nv_bfloat16* tl = which ? g_wo_lo : g_wq_lo;
    __shared__ float t[32][33];
    int n0 = blockIdx.x * 32, k0 = blockIdx.y * 32;
    int tx = threadIdx.x, ty = threadIdx.y;
#pragma unroll
    for (int i = 0; i < 4; i++)
        t[ty + 8 * i][tx] = w[(size_t)(k0 + ty + 8 * i) * N + n0 + tx];
    __syncthreads();
#pragma unroll
    for (int i = 0; i < 4; i++) {
        int n = n0 + ty + 8 * i;
        float v = t[tx][ty + 8 * i];
        __nv_bfloat16 h = __float2bfloat16(v);
        th[(size_t)n * K + k0 + tx] = h;
        tl[(size_t)n * K + k0 + tx] = __float2bfloat16(v - __bfloat162float(h));
    }
}

// V^T: [b,h,s,d] fp32 -> [b,h,d,s] fp16 hi/lo
__global__ void conv_vT() {
    __shared__ float t[32][33];
    int s0 = blockIdx.x * 32, d0 = blockIdx.y * 32, bh = blockIdx.z;
    const float* src = g_v + (size_t)bh * SS * DK;
    int tx = threadIdx.x, ty = threadIdx.y;
#pragma unroll
    for (int i = 0; i < 4; i++)
        t[ty + 8 * i][tx] = src[(size_t)(s0 + ty + 8 * i) * DK + d0 + tx];
    __syncthreads();
#pragma unroll
    for (int i = 0; i < 4; i++) {
        int d = d0 + ty + 8 * i;
        float v = t[tx][ty + 8 * i];                 // V[s0+tx][d]
        __half h = __float2half(v);
        g_vth[((size_t)bh * DK + d) * SS + s0 + tx] = h;
        g_vtl[((size_t)bh * DK + d) * SS + s0 + tx] =
            __float2half(v - __half2float(h));
    }
}

// --------------------- RoPE + bf16 hi/lo split (q scaled) -------------------
__global__ void rope_split_kernel() {
    int idx = blockIdx.x * blockDim.x + threadIdx.x;
    const int half_total = BB * NH * SS * (DK / 2);
    bool isq = idx < half_total;
    const float* arr = isq ? g_q : g_k;
    __nv_bfloat16* oh = isq ? g_qh : g_kh;
    __nv_bfloat16* ol = isq ? g_ql : g_kl;
    int p = idx & (half_total - 1);
    int d2 = p & 31;
    int s = (p >> 5) & (SS - 1);
    int bh = p >> 16;
    int off = (bh * SS + s) * DK + 2 * d2;
    float inv = powf(10000.0f, -(float)d2 * (1.0f / 32.0f));
    float ang = (float)s * inv;
    float c = cosf(ang), si = sinf(ang);
    float e = arr[off], o = arr[off + 1];
    float re = e * c - o * si;
    float ro = o * c + e * si;
    if (isq) { re *= 0.125f; ro *= 0.125f; }   // fold 1/sqrt(dk) into q
    __nv_bfloat16 he = __float2bfloat16(re);
    __nv_bfloat16 hoo = __float2bfloat16(ro);
    oh[off]     = he;
    oh[off + 1] = hoo;
    ol[off]     = __float2bfloat16(re - __bfloat162float(he));
    ol[off + 1] = __float2bfloat16(ro - __bfloat162float(hoo));
}

// ---------------- tensorized sliding-window attention (HMMA) ----------------
// CTA: (q-block 64, head, batch), 128 threads = 4 warps; warp w: rows w*16.
// S = QK^T via bf16x3 (q pre-scaled); softmax in fragment regs; PV via
// fp16 P (single) x fp16 V^T (hi/lo split). K/V double-buffered cp.async.
#define AT2_STR 72
#define AT2_TILEB (64 * AT2_STR * 2)             // 9216 bytes per tile
#define AT2_QBYTES (2 * AT2_TILEB)               // Qh, Ql
#define AT2_STAGEB (4 * AT2_TILEB)               // Kh, Kl, Vth, Vtl
#define AT2_SMEM (AT2_QBYTES + 2 * AT2_STAGEB)   // 92160 bytes

__device__ __forceinline__ void at_issue(char* stage, int tid, int bh, int k0) {
    const char* srcs[4] = {
        (const char*)(g_kh  + ((size_t)bh * SS + k0) * DK),
        (const char*)(g_kl  + ((size_t)bh * SS + k0) * DK),
        (const char*)(g_vth + (size_t)bh * DK * SS + k0),
        (const char*)(g_vtl + (size_t)bh * DK * SS + k0) };
    // tiles 0,1: row r -> g + r*DK elems ; tiles 2,3: row r(d) -> g + r*SS elems
#pragma unroll
    for (int i = 0; i < 16; i++) {
        int idx = tid + i * 128;
        int tile = idx >> 9;
        int rem = idx & 511;
        int r = rem >> 3, c16 = rem & 7;
        size_t srcoff = (tile < 2) ? ((size_t)r * DK + c16 * 8) * 2
                                   : ((size_t)r * SS + c16 * 8) * 2;
        cp_async16(smem_u32(stage + tile * AT2_TILEB + r * (AT2_STR * 2) + c16 * 16),
                   srcs[tile] + srcoff);
    }
    cp_commit();
}

__global__ __launch_bounds__(128) void attn_mma_kernel() {
    extern __shared__ char sm2[];
    __nv_bfloat16* Qh = (__nv_bfloat16*)sm2;
    __nv_bfloat16* Ql = (__nv_bfloat16*)(sm2 + AT2_TILEB);
    char* stage0 = sm2 + AT2_QBYTES;

    int tid = threadIdx.x;
    int wid = tid >> 5, lane = tid & 31;
    int qr = lane >> 2, qc = (lane & 3) * 2;
    int q0 = blockIdx.x * 64;
    int hh = blockIdx.y, b = blockIdx.z;
    int bh = b * NH + hh;

    // load Q tile (hi/lo) : 2 tiles x 512 x 16B
    {
        const char* qsrc[2] = { (const char*)(g_qh + ((size_t)bh * SS + q0) * DK),
                                (const char*)(g_ql + ((size_t)bh * SS + q0) * DK) };
#pragma unroll
        for (int i = 0; i < 8; i++) {
            int idx = tid + i * 128;
            int tile = idx >> 9;
            int rem = idx & 511;
            int r = rem >> 3, c16 = rem & 7;
            uint4 v = *(const uint4*)(qsrc[tile] + ((size_t)r * DK + c16 * 8) * 2);
            *(uint4*)(sm2 + tile * AT2_TILEB + r * (AT2_STR * 2) + c16 * 16) = v;
        }
    }

    float oreg[8][4];
    float m0 = -1e30f, m1 = -1e30f, l0 = 0.f, l1 = 0.f;
#pragma unroll
    for (int dt = 0; dt < 8; dt++)
#pragma unroll
        for (int k = 0; k < 4; k++) oreg[dt][k] = 0.f;

    int iq0 = q0 + wid * 16 + qr;       // row for c0,c1
    int iq1 = iq0 + 8;                  // row for c2,c3
    int iqmin = q0 + wid * 16;

    int first = (q0 >= WIN) ? (q0 - WIN) : 0;
    int ntiles = (q0 + 63 - first) / 64 + 1;

    at_issue(stage0, tid, bh, first);

    for (int t = 0; t < ntiles; t++) {
        int k0 = first + t * 64;
        asm volatile("cp.async.wait_group 0;" ::: "memory");
        __syncthreads();
        if (t + 1 < ntiles)
            at_issue(stage0 + ((t + 1) & 1) * AT2_STAGEB, tid, bh, k0 + 64);

        char* st = stage0 + (t & 1) * AT2_STAGEB;
        const __nv_bfloat16* Kh = (const __nv_bfloat16*)st;
        const __nv_bfloat16* Kl = (const __nv_bfloat16*)(st + AT2_TILEB);
        const __half* Vth = (const __half*)(st + 2 * AT2_TILEB);
        const __half* Vtl = (const __half*)(st + 3 * AT2_TILEB);

        // ---- S = Q K^T (bf16x3) ----
        float sreg[8][4];
#pragma unroll
        for (int nt = 0; nt < 8; nt++)
#pragma unroll
            for (int k = 0; k < 4; k++) sreg[nt][k] = 0.f;

#pragma unroll
        for (int kk = 0; kk < 4; kk++) {
            int kc = kk * 16 + qc;
            uint32_t aqh[4], aql[4];
            int arow = wid * 16 + qr;
            aqh[0] = *(const uint32_t*)(Qh + arow * AT2_STR + kc);
            aqh[1] = *(const uint32_t*)(Qh + (arow + 8) * AT2_STR + kc);
            aqh[2] = *(const uint32_t*)(Qh + arow * AT2_STR + kc + 8);
            aqh[3] = *(const uint32_t*)(Qh + (arow + 8) * AT2_STR + kc + 8);
            aql[0] = *(const uint32_t*)(Ql + arow * AT2_STR + kc);
            aql[1] = *(const uint32_t*)(Ql + (arow + 8) * AT2_STR + kc);
            aql[2] = *(const uint32_t*)(Ql + arow * AT2_STR + kc + 8);
            aql[3] = *(const uint32_t*)(Ql + (arow + 8) * AT2_STR + kc + 8);
#pragma unroll
            for (int nt = 0; nt < 8; nt++) {
                int brow = nt * 8 + qr;
                uint32_t bkh[2], bkl[2];
                bkh[0] = *(const uint32_t*)(Kh + brow * AT2_STR + kc);
                bkh[1] = *(const uint32_t*)(Kh + brow * AT2_STR + kc + 8);
                bkl[0] = *(const uint32_t*)(Kl + brow * AT2_STR + kc);
                bkl[1] = *(const uint32_t*)(Kl + brow * AT2_STR + kc + 8);
                mma_bf16(sreg[nt], aqh, bkh);
                mma_bf16(sreg[nt], aqh, bkl);
                mma_bf16(sreg[nt], aql, bkh);
            }
        }

        // ---- mask (scale already folded into q) ----
        bool full = (k0 + 63 <= iqmin) && (k0 >= iqmin + 15 - WIN);
        if (!full) {
#pragma unroll
            for (int nt = 0; nt < 8; nt++) {
                int jk = k0 + nt * 8 + qc;
#pragma unroll
                for (int e = 0; e < 2; e++) {
                    int j = jk + e;
                    if (!(j <= iq0 && j >= iq0 - WIN)) sreg[nt][e] = -1e30f;
                    if (!(j <= iq1 && j >= iq1 - WIN)) sreg[nt][2 + e] = -1e30f;
                }
            }
        }

        // ---- online softmax (rows iq0, iq1; 4-lane reductions) ----
        float t0 = -1e30f, t1 = -1e30f;
#pragma unroll
        for (int nt = 0; nt < 8; nt++) {
            t0 = fmaxf(t0, fmaxf(sreg[nt][0], sreg[nt][1]));
            t1 = fmaxf(t1, fmaxf(sreg[nt][2], sreg[nt][3]));
        }
        t0 = fmaxf(t0, __shfl_xor_sync(0xffffffffu, t0, 1));
        t0 = fmaxf(t0, __shfl_xor_sync(0xffffffffu, t0, 2));
        t1 = fmaxf(t1, __shfl_xor_sync(0xffffffffu, t1, 1));
        t1 = fmaxf(t1, __shfl_xor_sync(0xffffffffu, t1, 2));
        float mn0 = fmaxf(m0, t0), mn1 = fmaxf(m1, t1);
        float c0 = __expf(m0 - mn0), c1 = __expf(m1 - mn1);
        m0 = mn0; m1 = mn1;

        float ps0 = 0.f, ps1 = 0.f;
#pragma unroll
        for (int nt = 0; nt < 8; nt++) {
            sreg[nt][0] = __expf(sreg[nt][0] - mn0); ps0 += sreg[nt][0];
            sreg[nt][1] = __expf(sreg[nt][1] - mn0); ps0 += sreg[nt][1];
            sreg[nt][2] = __expf(sreg[nt][2] - mn1); ps1 += sreg[nt][2];
            sreg[nt][3] = __expf(sreg[nt][3] - mn1); ps1 += sreg[nt][3];
        }
        ps0 += __shfl_xor_sync(0xffffffffu, ps0, 1);
        ps0 += __shfl_xor_sync(0xffffffffu, ps0, 2);
        ps1 += __shfl_xor_sync(0xffffffffu, ps1, 1);
        ps1 += __shfl_xor_sync(0xffffffffu, ps1, 2);
        l0 = l0 * c0 + ps0;
        l1 = l1 * c1 + ps1;

#pragma unroll
        for (int dt = 0; dt < 8; dt++) {
            oreg[dt][0] *= c0; oreg[dt][1] *= c0;
            oreg[dt][2] *= c1; oreg[dt][3] *= c1;
        }

        // ---- P fragments (fp32 accum layout == A-frag layout) ----
        uint32_t pa[4][4];
#pragma unroll
        for (int u = 0; u < 4; u++) {
            pa[u][0] = pack_h2(sreg[2*u][0],     sreg[2*u][1]);
            pa[u][1] = pack_h2(sreg[2*u][2],     sreg[2*u][3]);
            pa[u][2] = pack_h2(sreg[2*u + 1][0], sreg[2*u + 1][1]);
            pa[u][3] = pack_h2(sreg[2*u + 1][2], sreg[2*u + 1][3]);
        }

        // ---- O += P V (fp16, V hi/lo) ----
#pragma unroll
        for (int u = 0; u < 4; u++) {
            int kc = u * 16 + qc;
#pragma unroll
            for (int dt = 0; dt < 8; dt++) {
                int brow = dt * 8 + qr;
                uint32_t bvh[2], bvl[2];
                bvh[0] = *(const uint32_t*)(Vth + brow * AT2_STR + kc);
                bvh[1] = *(const uint32_t*)(Vth + brow * AT2_STR + kc + 8);
                bvl[0] = *(const uint32_t*)(Vtl + brow * AT2_STR + kc);
                bvl[1] = *(const uint32_t*)(Vtl + brow * AT2_STR + kc + 8);
                mma_f16(oreg[dt], pa[u], bvh);
                mma_f16(oreg[dt], pa[u], bvl);
            }
        }
    }

    // ---- epilogue: normalize + bf16 hi/lo split into g_at ----
    float il0 = 1.0f / l0, il1 = 1.0f / l1;
    size_t base0 = ((size_t)b * SS + iq0) * DM + hh * DK;
    size_t base1 = ((size_t)b * SS + iq1) * DM + hh * DK;
#pragma unroll
    for (int dt = 0; dt < 8; dt++) {
        int d = dt * 8 + qc;
        float v0 = oreg[dt][0] * il0, v1 = oreg[dt][1] * il0;
        float v2 = oreg[dt][2] * il1, v3 = oreg[dt][3] * il1;
        __nv_bfloat162 h01, h23, e01, e23;
        h01.x = __float2bfloat16(v0); h01.y = __float2bfloat16(v1);
        h23.x = __float2bfloat16(v2); h23.y = __float2bfloat16(v3);
        e01.x = __float2bfloat16(v0 - __bfloat162float(h01.x));
        e01.y = __float2bfloat16(v1 - __bfloat162float(h01.y));
        e23.x = __float2bfloat16(v2 - __bfloat162float(h23.x));
        e23.y = __float2bfloat16(v3 - __bfloat162float(h23.y));
        *(__nv_bfloat162*)(g_at_hi + base0 + d) = h01;
        *(__nv_bfloat162*)(g_at_lo + base0 + d) = e01;
        *(__nv_bfloat162*)(g_at_hi + base1 + d) = h23;
        *(__nv_bfloat162*)(g_at_lo + base1 + d) = e23;
    }
}

// ---------------------------------------------------------------------------

extern "C" void kernel_launch(void* const* d_in, const int* in_sizes, int n_in,
                              void* d_out, int out_size) {
    const float* x     = (const float*)d_in[0];
    const float* w_qkv = (const float*)d_in[1];
    const float* w_o   = (const float*)d_in[2];
    float* out = (float*)d_out;

    cudaFuncSetAttribute(mma_gemm_qkv, cudaFuncAttributeMaxDynamicSharedMemorySize,
                         MM_SMEM_BYTES);
    cudaFuncSetAttribute(mma_gemm_out, cudaFuncAttributeMaxDynamicSharedMemorySize,
                         MM_SMEM_BYTES);
    cudaFuncSetAttribute(attn_mma_kernel, cudaFuncAttributeMaxDynamicSharedMemorySize,
                         AT2_SMEM);

    // 0) fp32 -> bf16 hi/lo splits
    conv_split<<<(BB * SS * DM) / (256 * 4), 256>>>(x);
    conv_wT<<<dim3(3 * DM / 32, DM / 32), dim3(32, 8)>>>(w_qkv, 0, DM, 3 * DM);
    conv_wT<<<dim3(DM / 32, DM / 32), dim3(32, 8)>>>(w_o, 1, DM, DM);

    // 1) QKV projection (bf16x3 HMMA, 2-stage, 2 CTA/SM)
    mma_gemm_qkv<<<dim3(3 * DM / 128, BB * SS / 128), 256, MM_SMEM_BYTES>>>();

    // 2) RoPE + bf16 split (q pre-scaled by 1/8); V^T fp16 split
    rope_split_kernel<<<(2 * BB * NH * SS * (DK / 2)) / 256, 256>>>();
    conv_vT<<<dim3(SS / 32, DK / 32, BB * NH), dim3(32, 8)>>>();

    // 3) tensorized sliding-window attention
    attn_mma_kernel<<<dim3(SS / 64, NH, BB), 128, AT2_SMEM>>>();

    // 4) output projection
    mma_gemm_out<<<dim3(DM / 128, BB * SS / 128), 256, MM_SMEM_BYTES>>>(out);
}